// round 1
// baseline (speedup 1.0000x reference)
#include <cuda_runtime.h>
#include <math.h>

// Problem constants
#define DCH   128      // D
#define STARTL 8       // ConvUpsample start length
#define BE    1024     // BATCH * N_EVENTS
#define NF    128      // N_FRAMES
#define NS    32768    // N_SAMPLES

// Shared memory layout (floats), dynamic:
//   P: 128*65 = 8320   (holds L=16-stride17?? no: P holds stride-17 and stride-65 stages)
//   Q: 128*33 = 4224
//   xf: 128, vseq: 128
#define P_OFF    0
#define P_SIZE   (128*65)
#define Q_OFF    (P_OFF + P_SIZE)
#define Q_SIZE   (128*33)
#define XF_OFF   (Q_OFF + Q_SIZE)
#define VSEQ_OFF (XF_OFF + 128)
#define SMEM_FLOATS (VSEQ_OFF + 128)
#define SMEM_BYTES  (SMEM_FLOATS * 4)

__device__ __forceinline__ float leaky(float v) { return v > 0.f ? v : 0.2f * v; }

// Transposed conv (k=4, s=2, p=1), JAX conv_transpose semantics (no kernel flip):
//   y[2j]   = sum_ci x[ci][j-1]*W[ci][co][0] + x[ci][j]*W[ci][co][2]
//   y[2j+1] = sum_ci x[ci][j]  *W[ci][co][1] + x[ci][j+1]*W[ci][co][3]
// xin has row stride LIN+1, yout has row stride 2*LIN+1 (bank-conflict padding).
template <int LIN>
__device__ __forceinline__ void tconv_layer(
    const float* __restrict__ W, const float* __restrict__ bias,
    const float* __restrict__ xin, float* __restrict__ yout,
    int co, bool act)
{
    constexpr int LOUT = 2 * LIN;
    float acc[LOUT];
    const float bv = bias[co];
#pragma unroll
    for (int l = 0; l < LOUT; ++l) acc[l] = bv;

    for (int ci = 0; ci < DCH; ++ci) {
        float4 w = *(const float4*)(W + ((ci * DCH + co) << 2));
        const float* xr = xin + ci * (LIN + 1);
        float xm1 = 0.f;
#pragma unroll
        for (int j = 0; j < LIN; ++j) {
            float xj  = xr[j];
            float xp1 = (j + 1 < LIN) ? xr[j + 1] : 0.f;
            acc[2 * j]     += xm1 * w.x + xj * w.z;
            acc[2 * j + 1] += xj * w.y + xp1 * w.w;
            xm1 = xj;
        }
    }
#pragma unroll
    for (int l = 0; l < LOUT; ++l) {
        float v = acc[l];
        yout[co * (LOUT + 1) + l] = act ? leaky(v) : v;
    }
}

__global__ void __launch_bounds__(128) npg_kernel(
    const float* __restrict__ x,    const float* __restrict__ noise,
    const float* __restrict__ Wup,  const float* __restrict__ bup,
    const float* __restrict__ Wd0,  const float* __restrict__ bd0,
    const float* __restrict__ Wd1,  const float* __restrict__ bd1,
    const float* __restrict__ Wd2,  const float* __restrict__ bd2,
    const float* __restrict__ Wdo,  const float* __restrict__ bdo,
    const float* __restrict__ Wc0,  const float* __restrict__ bc0,
    const float* __restrict__ Wc1,  const float* __restrict__ bc1,
    const float* __restrict__ Wc2,  const float* __restrict__ bc2,
    const float* __restrict__ Wc3,  const float* __restrict__ bc3,
    float* __restrict__ out)
{
    extern __shared__ float smem[];
    float* P    = smem + P_OFF;     // big ping buffer (stride-17 and stride-65 stages)
    float* Q    = smem + Q_OFF;     // pong buffer (decay hidden, stride-9, stride-33 stages)
    float* xf   = smem + XF_OFF;
    float* vseq = smem + VSEQ_OFF;
    __shared__ float s_red[4];
    __shared__ float s_decay;

    const int row  = blockIdx.x;
    const int t    = threadIdx.x;
    const int lane = t & 31;
    const int warp = t >> 5;

    xf[t] = x[row * DCH + t];
    __syncthreads();

    // ---------------- decay head: 3x (D->D leaky) -> D->1 sigmoid ----------------
    {
        float* h0 = Q;
        float* h1 = Q + DCH;
        h0[t] = xf[t];
        __syncthreads();
        const float* Ws[3] = {Wd0, Wd1, Wd2};
        const float* bs[3] = {bd0, bd1, bd2};
        float* cur = h0;
        float* nxt = h1;
        for (int L = 0; L < 3; ++L) {
            float a = bs[L][t];
            const float* W = Ws[L];
            for (int dd = 0; dd < DCH; ++dd) a += cur[dd] * W[dd * DCH + t];
            nxt[t] = leaky(a);            // disjoint buffers: safe to write before sync
            __syncthreads();
            float* tmp = cur; cur = nxt; nxt = tmp;
        }
        float p = cur[t] * Wdo[t];
#pragma unroll
        for (int off = 16; off > 0; off >>= 1) p += __shfl_xor_sync(0xffffffffu, p, off);
        if (lane == 0) s_red[warp] = p;
        __syncthreads();
        if (t == 0) {
            float s = s_red[0] + s_red[1] + s_red[2] + s_red[3] + bdo[0];
            s_decay = 0.8f + 0.2f / (1.f + expf(-s));
        }
        __syncthreads();
    }

    // ---------------- up projection: xf @ Wup -> [128][8] into Q (stride 9) ------
    {
        float a[STARTL];
        {
            float4 b0 = *(const float4*)(bup + t * 8);
            float4 b1 = *(const float4*)(bup + t * 8 + 4);
            a[0] = b0.x; a[1] = b0.y; a[2] = b0.z; a[3] = b0.w;
            a[4] = b1.x; a[5] = b1.y; a[6] = b1.z; a[7] = b1.w;
        }
        for (int dd = 0; dd < DCH; ++dd) {
            float xv = xf[dd];
            const float* wr = Wup + dd * (DCH * STARTL) + t * 8;
            float4 w0 = *(const float4*)(wr);
            float4 w1 = *(const float4*)(wr + 4);
            a[0] += xv * w0.x; a[1] += xv * w0.y; a[2] += xv * w0.z; a[3] += xv * w0.w;
            a[4] += xv * w1.x; a[5] += xv * w1.y; a[6] += xv * w1.z; a[7] += xv * w1.w;
        }
        __syncthreads();   // decay phase reads of Q fully done (barrier above covers)
#pragma unroll
        for (int l = 0; l < STARTL; ++l) Q[t * 9 + l] = a[l];
        __syncthreads();
    }

    // ---------------- transposed conv stack: 8 -> 16 -> 32 -> 64 -----------------
    tconv_layer<8>(Wc0, bc0, Q, P, t, true);
    __syncthreads();
    tconv_layer<16>(Wc1, bc1, P, Q, t, true);
    __syncthreads();
    tconv_layer<32>(Wc2, bc2, Q, P, t, true);
    __syncthreads();

    // ---------------- final tconv to 1 channel (64 -> 128), square ---------------
    {
        const int o    = t;
        const int j    = o >> 1;
        const bool ev  = (o & 1) == 0;
        const int ia   = ev ? (j - 1) : j;
        const int ib   = ev ? j : (j + 1);
        const bool va  = ia >= 0;
        const bool vb  = ib <= 63;
        float acc = bc3[0];
        for (int ci = 0; ci < DCH; ++ci) {
            float4 w = *(const float4*)(Wc3 + (ci << 2));
            const float* xr = P + ci * 65;
            float xa = va ? xr[ia] : 0.f;
            float xb = vb ? xr[ib] : 0.f;
            float ca = ev ? w.x : w.y;
            float cb = ev ? w.z : w.w;
            acc += xa * ca + xb * cb;
        }
        vseq[t] = acc * acc;
    }
    __syncthreads();

    // ---------------- exponential decay recurrence (serial, 128 steps) -----------
    if (t == 0) {
        float v = 0.f;
        const float dc = s_decay;
        for (int f = 0; f < NF; ++f) { v = vseq[f] + dc * v; vseq[f] = v; }
    }
    __syncthreads();

    // ---------------- linear interp 128 -> 32768, multiply by noise --------------
    {
        const float4* np_ = (const float4*)(noise + (size_t)row * NS);
        float4*       op  = (float4*)(out + (size_t)row * NS);
        for (int i4 = t; i4 < NS / 4; i4 += 128) {
            float4 nz = np_[i4];
            int n0 = i4 << 2;
            float4 r;
#pragma unroll
            for (int k = 0; k < 4; ++k) {
                // pos = (n+0.5)/256 - 0.5 = n/256 - 0.498046875 (exact in fp32)
                float pos = fmaf((float)(n0 + k), 0.00390625f, -0.498046875f);
                pos = fminf(fmaxf(pos, 0.f), 127.f);
                int   i0 = (int)pos;
                float w  = pos - (float)i0;
                int   i1 = min(i0 + 1, NF - 1);
                float val = vseq[i0] * (1.f - w) + vseq[i1] * w;
                ((float*)&r)[k] = val * ((const float*)&nz)[k];
            }
            op[i4] = r;
        }
    }
}

extern "C" void kernel_launch(void* const* d_in, const int* in_sizes, int n_in,
                              void* d_out, int out_size)
{
    (void)in_sizes; (void)n_in; (void)out_size;
    const float* x    = (const float*)d_in[0];
    const float* noise= (const float*)d_in[1];
    const float* Wup  = (const float*)d_in[2];
    const float* bup  = (const float*)d_in[3];
    const float* Wd0  = (const float*)d_in[4];
    const float* bd0  = (const float*)d_in[5];
    const float* Wd1  = (const float*)d_in[6];
    const float* bd1  = (const float*)d_in[7];
    const float* Wd2  = (const float*)d_in[8];
    const float* bd2  = (const float*)d_in[9];
    const float* Wdo  = (const float*)d_in[10];
    const float* bdo  = (const float*)d_in[11];
    const float* Wc0  = (const float*)d_in[12];
    const float* bc0  = (const float*)d_in[13];
    const float* Wc1  = (const float*)d_in[14];
    const float* bc1  = (const float*)d_in[15];
    const float* Wc2  = (const float*)d_in[16];
    const float* bc2  = (const float*)d_in[17];
    const float* Wc3  = (const float*)d_in[18];
    const float* bc3  = (const float*)d_in[19];
    float* out = (float*)d_out;

    cudaFuncSetAttribute(npg_kernel, cudaFuncAttributeMaxDynamicSharedMemorySize, SMEM_BYTES);
    npg_kernel<<<BE, 128, SMEM_BYTES>>>(
        x, noise, Wup, bup, Wd0, bd0, Wd1, bd1, Wd2, bd2, Wdo, bdo,
        Wc0, bc0, Wc1, bc1, Wc2, bc2, Wc3, bc3, out);
}